// round 10
// baseline (speedup 1.0000x reference)
#include <cuda_runtime.h>
#include <cuda_bf16.h>

#define Nn 100000
#define Ee 600000
#define Dd 128
#define Gg 256
#define EPSV 1e-5f

typedef unsigned long long ull;
typedef unsigned int uint32;

// ---------------- scratch (device globals; no allocation allowed) ----------------
__device__ __align__(16) float d_h[Nn * Dd];     // normed features (GEMM input + gather source)
__device__ __align__(16) float d_agg[Nn * Dd];   // segment-max result
__device__ __align__(16) float d_y[Nn * Dd];     // relu(x + sage) pre-norm2
__device__ __align__(16) float d_s1[Gg * Dd], d_q1[Gg * Dd];
__device__ __align__(16) float d_s2[Gg * Dd], d_q2[Gg * Dd];
__device__ __align__(16) float d_A1[Gg * Dd], d_C1[Gg * Dd];
__device__ __align__(16) float d_A2[Gg * Dd], d_C2[Gg * Dd];
__device__ float d_cnt[Gg];
__device__ int d_deg[Nn], d_start[Nn], d_cur[Nn], d_srcs[Ee];
__device__ int d_bsum[128];

// ---------------- zero scratch ----------------
__global__ void zeroKernel() {
    int i = blockIdx.x * blockDim.x + threadIdx.x;
    int stride = gridDim.x * blockDim.x;
    for (int j = i; j < Gg * Dd; j += stride) { d_s1[j] = 0.f; d_q1[j] = 0.f; d_s2[j] = 0.f; d_q2[j] = 0.f; }
    for (int j = i; j < Gg; j += stride) d_cnt[j] = 0.f;
    for (int j = i; j < Nn; j += stride) d_deg[j] = 0;
}

// ---------------- per-graph moments (batch is SORTED int32: register-accumulate, flush on boundary)
__global__ void momentsKernel(const float* __restrict__ xin, const int* __restrict__ batch,
                              int pass) {
    const float* x = pass ? (const float*)d_y : xin;
    float* sum = pass ? d_s2 : d_s1;
    float* sq = pass ? d_q2 : d_q1;
    int doCnt = (pass == 0);
    int lane = threadIdx.x;                       // 0..31 -> dims lane*4..lane*4+3
    int r0 = blockIdx.x * 256 + threadIdx.y * 32; // this stream's first row
    float4 a = make_float4(0.f, 0.f, 0.f, 0.f);
    float4 q = make_float4(0.f, 0.f, 0.f, 0.f);
    float c = 0.f;
    int curg = -1;

#define FLUSH_MOM()                                                             \
    {                                                                           \
        int base = curg * Dd + lane * 4;                                        \
        atomicAdd(&sum[base + 0], a.x); atomicAdd(&sum[base + 1], a.y);         \
        atomicAdd(&sum[base + 2], a.z); atomicAdd(&sum[base + 3], a.w);         \
        atomicAdd(&sq[base + 0], q.x);  atomicAdd(&sq[base + 1], q.y);          \
        atomicAdd(&sq[base + 2], q.z);  atomicAdd(&sq[base + 3], q.w);          \
        if (doCnt && lane == 0) atomicAdd(&d_cnt[curg], c);                     \
    }

    for (int i = 0; i < 32; i++) {
        int r = r0 + i;
        if (r >= Nn) break;
        int g = __ldg(&batch[r]);
        if (g != curg) {
            if (curg >= 0) FLUSH_MOM();
            curg = g;
            a = make_float4(0.f, 0.f, 0.f, 0.f);
            q = make_float4(0.f, 0.f, 0.f, 0.f);
            c = 0.f;
        }
        float4 v = ((const float4*)x)[r * 32 + lane];
        a.x += v.x; a.y += v.y; a.z += v.z; a.w += v.w;
        q.x += v.x * v.x; q.y += v.y * v.y; q.z += v.z * v.z; q.w += v.w * v.w;
        c += 1.f;
    }
    if (curg >= 0) FLUSH_MOM();
#undef FLUSH_MOM
}

// ---------------- fold moments into affine (h = A*x + C) ----------------
__global__ void statsKernel(const float* __restrict__ w, const float* __restrict__ b,
                            const float* __restrict__ ms, int pass) {
    const float* sum = pass ? d_s2 : d_s1;
    const float* sq = pass ? d_q2 : d_q1;
    float* A = pass ? d_A2 : d_A1;
    float* C = pass ? d_C2 : d_C1;
    int i = blockIdx.x * blockDim.x + threadIdx.x;
    if (i >= Gg * Dd) return;
    int g = i >> 7, dch = i & 127;
    float cnt = fmaxf(d_cnt[g], 1.f);
    float mean = sum[i] / cnt;
    float ex2 = sq[i] / cnt;
    float m = ms[dch];
    float var = ex2 - (2.f * m - m * m) * mean * mean;
    float rstd = rsqrtf(var + EPSV);
    float aa = w[dch] * rstd;
    A[i] = aa;
    C[i] = b[dch] - mean * m * aa;
}

// ---------------- apply affine per node ----------------
__global__ void affineKernel(const float* __restrict__ xin, const int* __restrict__ batch,
                             float* __restrict__ dout, int pass) {
    const float* in = pass ? (const float*)d_y : xin;
    float* out = pass ? dout : (float*)d_h;
    const float* A = pass ? d_A2 : d_A1;
    const float* C = pass ? d_C2 : d_C1;
    int i = blockIdx.x * blockDim.x + threadIdx.x;  // float4 index
    if (i >= Nn * 32) return;
    int r = i >> 5, col = i & 31;
    int g = __ldg(&batch[r]);
    float4 v = ((const float4*)in)[i];
    float4 a = ((const float4*)A)[g * 32 + col];
    float4 c = ((const float4*)C)[g * 32 + col];
    float4 o;
    o.x = fmaf(a.x, v.x, c.x); o.y = fmaf(a.y, v.y, c.y);
    o.z = fmaf(a.z, v.z, c.z); o.w = fmaf(a.w, v.w, c.w);
    ((float4*)out)[i] = o;
}

// ---------------- CSR build: degree -> scan -> scatter ----------------
__global__ void degreeKernel(const int* __restrict__ ei) {
    int i = blockIdx.x * blockDim.x + threadIdx.x;
    if (i < Ee) atomicAdd(&d_deg[ei[Ee + i]], 1);
}

__global__ void scanBlocks() {  // 98 blocks x 1024 threads, exclusive scan within block
    __shared__ int wt[32];
    int i = blockIdx.x * 1024 + threadIdx.x;
    int v = (i < Nn) ? d_deg[i] : 0;
    int lane = threadIdx.x & 31, wd = threadIdx.x >> 5;
    int inc = v;
#pragma unroll
    for (int o = 1; o < 32; o <<= 1) {
        int t = __shfl_up_sync(0xffffffffu, inc, o);
        if (lane >= o) inc += t;
    }
    if (lane == 31) wt[wd] = inc;
    __syncthreads();
    if (wd == 0) {
        int t = wt[lane];
#pragma unroll
        for (int o = 1; o < 32; o <<= 1) {
            int u = __shfl_up_sync(0xffffffffu, t, o);
            if (lane >= o) t += u;
        }
        wt[lane] = t;
    }
    __syncthreads();
    int base = (wd > 0) ? wt[wd - 1] : 0;
    if (i < Nn) d_start[i] = base + inc - v;
    if (threadIdx.x == 1023) d_bsum[blockIdx.x] = base + inc;
}

__global__ void scanBsums() {  // 1 block, 128 threads; 98 valid entries -> exclusive
    __shared__ int s[128];
    int t = threadIdx.x;
    int v = (t < 98) ? d_bsum[t] : 0;
    s[t] = v;
    __syncthreads();
    for (int o = 1; o < 128; o <<= 1) {
        int u = (t >= o) ? s[t - o] : 0;
        __syncthreads();
        s[t] += u;
        __syncthreads();
    }
    if (t < 98) d_bsum[t] = s[t] - v;
}

__global__ void fixupKernel() {
    int i = blockIdx.x * blockDim.x + threadIdx.x;
    if (i < Nn) {
        int st = d_start[i] + d_bsum[i >> 10];
        d_start[i] = st;
        d_cur[i] = st;
    }
}

__global__ void scatterKernel(const int* __restrict__ ei) {
    int i = blockIdx.x * blockDim.x + threadIdx.x;
    if (i < Ee) {
        int dst = ei[Ee + i];
        int p = atomicAdd(&d_cur[dst], 1);
        d_srcs[p] = ei[i];
    }
}

// ---------------- segment-max aggregation: one warp per node ----------------
__global__ void aggKernel() {
    int w = (blockIdx.x * blockDim.x + threadIdx.x) >> 5;
    int lane = threadIdx.x & 31;
    if (w >= Nn) return;
    int s = d_start[w], dg = d_deg[w];
    float4 acc = make_float4(-3.0e38f, -3.0e38f, -3.0e38f, -3.0e38f);
    for (int base = 0; base < dg; base += 32) {
        int rem = dg - base;
        if (rem > 32) rem = 32;
        int sc = (lane < rem) ? d_srcs[s + base + lane] : 0;
        for (int j = 0; j < rem; j++) {
            int scj = __shfl_sync(0xffffffffu, sc, j);
            float4 v = ((const float4*)d_h)[scj * 32 + lane];
            acc.x = fmaxf(acc.x, v.x); acc.y = fmaxf(acc.y, v.y);
            acc.z = fmaxf(acc.z, v.z); acc.w = fmaxf(acc.w, v.w);
        }
    }
    if (dg == 0) acc = make_float4(0.f, 0.f, 0.f, 0.f);  // PyG: empty segments -> 0
    ((float4*)d_agg)[w * 32 + lane] = acc;
}

// ================= tensor-core GEMM (bf16 split, HMMA mma.sync) =================
// y = relu(x + agg@wl^T + b_l + h@wr^T) with error-compensated bf16 split:
//   acc = aHi*wHi + aHi*wLo + aLo*wHi   (lo*lo dropped, ~2^-16 relative)
// ONE smem fill per k-chunk serves ALL THREE segments: stage aHi/aLo/bHi/bLo
// simultaneously (k-chunk = 32 -> 4 x 8 KB = 32 KB static smem), issue 6 HMMA
// per (kstep, n8) from the resident tiles. Fill iterations 384 -> 128 vs R9,
// syncthreads 24 -> 16, gmem A/W traffic and cvt work both 3x lower.
// Block: 128 rows x 128 cols, 256 threads (8 warps, each m32 x n64).
// Fragments PRE-PERMUTED at fill: 1 LDS.128 per A-frag, 1 LDS.64 per B-frag.

__device__ __forceinline__ uint32 packbf(float lo, float hi) {
    uint32 r;
    asm("cvt.rn.bf16x2.f32 %0, %1, %2;" : "=r"(r) : "f"(hi), "f"(lo));
    return r;
}

__device__ __forceinline__ void mma16816(float* c, const uint32* a, const uint32* b) {
    asm volatile(
        "mma.sync.aligned.m16n8k16.row.col.f32.bf16.bf16.f32 "
        "{%0,%1,%2,%3}, {%4,%5,%6,%7}, {%8,%9}, {%0,%1,%2,%3};"
        : "+f"(c[0]), "+f"(c[1]), "+f"(c[2]), "+f"(c[3])
        : "r"(a[0]), "r"(a[1]), "r"(a[2]), "r"(a[3]), "r"(b[0]), "r"(b[1]));
}

__global__ __launch_bounds__(256) void gemmKernel(const float* __restrict__ wl,
                                                  const float* __restrict__ wr,
                                                  const float* __restrict__ bl,
                                                  const float* __restrict__ x) {
    // aS: [m16 0..7][kstep 0..1][lane][4 u32] = 2048 u32 = 8 KB each
    // bS: [kstep 0..1][n8 0..15][lane][2 u32] = 2048 u32 = 8 KB each
    __shared__ __align__(16) uint32 aHiS[2048], aLoS[2048];
    __shared__ __align__(16) uint32 bHiS[2048], bLoS[2048];

    int tid = threadIdx.x;
    int lane = tid & 31, wid = tid >> 5;
    int warpM = wid >> 1, warpN = wid & 1;
    int r0 = blockIdx.x * 128;

    float acc[2][8][4];
#pragma unroll
    for (int mi = 0; mi < 2; mi++)
#pragma unroll
        for (int j = 0; j < 8; j++)
#pragma unroll
            for (int q = 0; q < 4; q++) acc[mi][j][q] = 0.f;

    for (int c = 0; c < 8; c++) {
        const float* srcA = (c < 4) ? (const float*)d_agg : (const float*)d_h;
        const float* srcW = (c < 4) ? wl : wr;
        int koff = (c & 3) * 32;

        __syncthreads();  // previous chunk's compute done before refill

        // ---- fill A hi+lo fragments (coalesced float2 gmem reads, one pass) ----
#pragma unroll
        for (int it = 0; it < 8; it++) {
            int idx = tid + it * 256;           // 0..2047 (row, k-pair)
            int row = idx >> 4, kp = idx & 15;
            int r = r0 + row;
            float2 v = make_float2(0.f, 0.f);
            if (r < Nn) v = *(const float2*)(srcA + r * 128 + koff + kp * 2);
            float h0 = __bfloat162float(__float2bfloat16(v.x));
            float h1 = __bfloat162float(__float2bfloat16(v.y));
            int m16 = row >> 4, rr = row & 15;
            int kstep = kp >> 3, p = kp & 7;
            int t = (rr & 7) * 4 + (p & 3);
            int reg = (rr >> 3) + ((p >> 2) << 1);
            int off = ((m16 * 2 + kstep) * 32 + t) * 4 + reg;
            aHiS[off] = packbf(v.x, v.y);
            aLoS[off] = packbf(v.x - h0, v.y - h1);
        }
        // ---- fill B hi+lo fragments ----
#pragma unroll
        for (int it = 0; it < 8; it++) {
            int idx = tid + it * 256;           // (n, k-pair)
            int n = idx >> 4, kp = idx & 15;
            float2 v = *(const float2*)(srcW + n * 128 + koff + kp * 2);
            float h0 = __bfloat162float(__float2bfloat16(v.x));
            float h1 = __bfloat162float(__float2bfloat16(v.y));
            int kstep = kp >> 3, p = kp & 7;
            int n8 = n >> 3, nn = n & 7;
            int t = nn * 4 + (p & 3);
            int reg = p >> 2;
            int off = ((kstep * 16 + n8) * 32 + t) * 2 + reg;
            bHiS[off] = packbf(v.x, v.y);
            bLoS[off] = packbf(v.x - h0, v.y - h1);
        }
        __syncthreads();

        // ---- mainloop: 2 ksteps x 8 n8 x 6 HMMA per warp (hi*hi + hi*lo + lo*hi) ----
#pragma unroll
        for (int kstep = 0; kstep < 2; kstep++) {
            uint32 ah[2][4], al[2][4];
#pragma unroll
            for (int mi = 0; mi < 2; mi++) {
                int m16 = warpM * 2 + mi;
                int off = ((m16 * 2 + kstep) * 32 + lane) * 4;
                *(uint4*)ah[mi] = *(const uint4*)&aHiS[off];
                *(uint4*)al[mi] = *(const uint4*)&aLoS[off];
            }
#pragma unroll
            for (int j = 0; j < 8; j++) {
                int off = ((kstep * 16 + warpN * 8 + j) * 32 + lane) * 2;
                uint32 bh[2], blo[2];
                *(uint2*)bh = *(const uint2*)&bHiS[off];
                *(uint2*)blo = *(const uint2*)&bLoS[off];
                mma16816(acc[0][j], ah[0], bh);
                mma16816(acc[1][j], ah[1], bh);
                mma16816(acc[0][j], ah[0], blo);
                mma16816(acc[1][j], ah[1], blo);
                mma16816(acc[0][j], al[0], bh);
                mma16816(acc[1][j], al[1], bh);
            }
        }
    }

    // ---- epilogue: bias + residual + relu -> d_y ----
#pragma unroll
    for (int mi = 0; mi < 2; mi++) {
        int rbase = r0 + warpM * 32 + mi * 16 + (lane >> 2);
#pragma unroll
        for (int j = 0; j < 8; j++) {
            int nc = warpN * 64 + j * 8 + (lane & 3) * 2;
            float b0 = __ldg(&bl[nc]), b1 = __ldg(&bl[nc + 1]);
            int r = rbase;
            if (r < Nn) {
                float2 xv = *(const float2*)(x + r * 128 + nc);
                float2 o;
                o.x = fmaxf(acc[mi][j][0] + b0 + xv.x, 0.f);
                o.y = fmaxf(acc[mi][j][1] + b1 + xv.y, 0.f);
                *(float2*)(d_y + r * 128 + nc) = o;
            }
            r = rbase + 8;
            if (r < Nn) {
                float2 xv = *(const float2*)(x + r * 128 + nc);
                float2 o;
                o.x = fmaxf(acc[mi][j][2] + b0 + xv.x, 0.f);
                o.y = fmaxf(acc[mi][j][3] + b1 + xv.y, 0.f);
                *(float2*)(d_y + r * 128 + nc) = o;
            }
        }
    }
}

// ---------------- launch (capture-safe: kernel launches ONLY) ----------------
extern "C" void kernel_launch(void* const* d_in, const int* in_sizes, int n_in,
                              void* d_out, int out_size) {
    const float* x = (const float*)d_in[0];
    const int* ei = (const int*)d_in[1];      // int32 (JAX x64 disabled)
    const int* batch = (const int*)d_in[2];   // int32
    const float* n1w = (const float*)d_in[3];
    const float* n1b = (const float*)d_in[4];
    const float* n1ms = (const float*)d_in[5];
    const float* n2w = (const float*)d_in[6];
    const float* n2b = (const float*)d_in[7];
    const float* n2ms = (const float*)d_in[8];
    const float* wl = (const float*)d_in[9];
    const float* bl = (const float*)d_in[10];
    const float* wr = (const float*)d_in[11];
    float* out = (float*)d_out;

    zeroKernel<<<512, 256>>>();
    // ---- GraphNorm 1: x -> d_h ----
    momentsKernel<<<391, dim3(32, 8)>>>(x, batch, 0);
    statsKernel<<<128, 256>>>(n1w, n1b, n1ms, 0);
    affineKernel<<<12500, 256>>>(x, batch, out, 0);   // pass 0 writes d_h internally
    // ---- CSR build (by dst) ----
    degreeKernel<<<2344, 256>>>(ei);
    scanBlocks<<<98, 1024>>>();
    scanBsums<<<1, 128>>>();
    fixupKernel<<<391, 256>>>();
    scatterKernel<<<2344, 256>>>(ei);
    // ---- segment-max aggregation ----
    aggKernel<<<12500, 256>>>();
    // ---- fused SAGE GEMMs + bias + residual + relu -> d_y (tensor cores) ----
    gemmKernel<<<782, 256>>>(wl, wr, bl, x);
    // ---- GraphNorm 2: d_y -> out ----
    momentsKernel<<<391, dim3(32, 8)>>>(x, batch, 1); // pass 1 reads d_y internally
    statsKernel<<<128, 256>>>(n2w, n2b, n2ms, 1);
    affineKernel<<<12500, 256>>>(x, batch, out, 1);   // pass 1 reads d_y, writes out
}